// round 3
// baseline (speedup 1.0000x reference)
#include <cuda_runtime.h>
#include <math.h>

#define BD   1024
#define HD   512
#define G4   2048
#define TENC 384
#define TDEC 128
#define ID   128
#define NBLK 128
#define NTHR 256

// ---------------- static device scratch (no allocations anywhere) ----------
__device__ float g_z  [BD * G4];     // gate pre-activations (8 MB)
__device__ float g_h01[BD * 1024];   // [h0 | h1] concatenated per batch row
__device__ float g_c0 [BD * HD];
__device__ float g_c1 [BD * HD];
__device__ float g_din[BD * ID];
__device__ unsigned           g_bar_cnt;   // zero-init
__device__ volatile unsigned  g_bar_gen;   // zero-init

// ---------------- helpers --------------------------------------------------
__device__ __forceinline__ unsigned f2tf(float f) {
    unsigned u;
    asm("cvt.rna.tf32.f32 %0, %1;" : "=r"(u) : "f"(f));
    return u;
}

__device__ __forceinline__ void mma8(float* c,
                                     unsigned a0, unsigned a1, unsigned a2, unsigned a3,
                                     unsigned b0, unsigned b1)
{
    asm volatile("mma.sync.aligned.m16n8k8.row.col.f32.tf32.tf32.f32 "
                 "{%0,%1,%2,%3}, {%4,%5,%6,%7}, {%8,%9}, {%0,%1,%2,%3};"
                 : "+f"(c[0]), "+f"(c[1]), "+f"(c[2]), "+f"(c[3])
                 : "r"(a0), "r"(a1), "r"(a2), "r"(a3), "r"(b0), "r"(b1));
}

__device__ __forceinline__ float sigf(float x) { return 1.f / (1.f + expf(-x)); }

// Software grid barrier (sense-reversing; all NBLK CTAs co-resident).
__device__ __forceinline__ void gridbar()
{
    __syncthreads();
    if (threadIdx.x == 0) {
        unsigned gen = g_bar_gen;
        __threadfence();
        if (atomicAdd(&g_bar_cnt, 1u) == NBLK - 1u) {
            g_bar_cnt = 0u;
            __threadfence();
            g_bar_gen = gen + 1u;
        } else {
            while (g_bar_gen == gen) { __nanosleep(64); }
        }
        __threadfence();
    }
    __syncthreads();
}

// ---------------- init phase -----------------------------------------------
__device__ void init_phase(const float* __restrict__ x)
{
    const int g = blockIdx.x * NTHR + threadIdx.x;         // 0..32767
#pragma unroll
    for (int i = 0; i < 32; i++) g_h01[g + i * (NBLK * NTHR)] = 0.f;
#pragma unroll
    for (int i = 0; i < 16; i++) {
        g_c0[g + i * (NBLK * NTHR)] = 0.f;
        g_c1[g + i * (NBLK * NTHR)] = 0.f;
    }
#pragma unroll
    for (int i = 0; i < 4; i++) {
        int idx = g + i * (NBLK * NTHR);
        int b = idx >> 7, col = idx & 127;
        float v = x[(size_t)b * (TENC * ID) + (size_t)(TENC - 1) * ID + col];
        g_din[idx] = __uint_as_float(f2tf(v));
    }
}

// ---------------- GEMM phase -----------------------------------------------
// Z[1024,2048] = concat_k( A1[:, :K1], A2[:, :KT-K1] ) @ concat(W1|W2)^T + bias
// Block = one 128x128 tile (8 m-tiles x 16 n-tiles = 128 blocks).
// smem layout per row (16 k): k interleaved into chunks c = k&3 holding
// {c, c+4, c+8, c+12}, chunk XOR-swizzled by row: phys = (c + row) & 3.
// => every mma fragment (A and B) is one conflict-free LDS.128.
template<int KT, int K1>
__device__ void gemm_phase(float* __restrict__ sbuf,
                           const float* __restrict__ A1, int lda1,
                           const float* __restrict__ A2, int lda2,
                           const float* __restrict__ W1,
                           const float* __restrict__ W2,
                           const float* __restrict__ bih,
                           const float* __restrict__ bhh)
{
    constexpr int K2 = KT - K1;
    float* As = sbuf;
    float* Ws = sbuf + 2048;

    const int tid = threadIdx.x;
    const int m0 = (blockIdx.x >> 4) * 128;
    const int n0 = (blockIdx.x & 15) * 128;

    // ---- fill mapping: thread handles float4 units f=tid and f=tid+256 ----
    const int fq  = tid & 3;        // global k-chunk within k-tile (k = kt + fq*4 ..+3)
    const int fm0 = tid >> 2;       // row 0..63
    const int fm1 = fm0 + 64;       // row 64..127

    const float* a1p0 = A1 + (size_t)(m0 + fm0) * lda1 + fq * 4;
    const float* a1p1 = A1 + (size_t)(m0 + fm1) * lda1 + fq * 4;
    const float* a2p0 = A2 + (size_t)(m0 + fm0) * lda2 + fq * 4 - K1;
    const float* a2p1 = A2 + (size_t)(m0 + fm1) * lda2 + fq * 4 - K1;
    const float* w1p0 = W1 + (size_t)(n0 + fm0) * K1 + fq * 4;
    const float* w1p1 = W1 + (size_t)(n0 + fm1) * K1 + fq * 4;
    const float* w2p0 = W2 + (size_t)(n0 + fm0) * K2 + fq * 4 - K1;
    const float* w2p1 = W2 + (size_t)(n0 + fm1) * K2 + fq * 4 - K1;

    float* sa0 = As + fm0 * 16 + fq;
    float* sa1 = As + fm1 * 16 + fq;
    float* sw0 = Ws + fm0 * 16 + fq;
    float* sw1 = Ws + fm1 * 16 + fq;

    // ---- fragment smem offsets (constant across k-tiles) ----
    const int lane = tid & 31, gid = lane >> 2, t4 = lane & 3;
    const int warp = tid >> 5;
    const int wm = (warp >> 2) * 64;
    const int wn = (warp & 3) * 32;
    int aoff[4], boff[4];
#pragma unroll
    for (int mi = 0; mi < 4; mi++) {
        int rl = wm + mi * 16 + gid;
        aoff[mi] = rl * 16 + ((t4 + rl) & 3) * 4;
    }
#pragma unroll
    for (int ni = 0; ni < 4; ni++) {
        int nr = wn + ni * 8 + gid;
        boff[ni] = nr * 16 + ((t4 + nr) & 3) * 4;
    }

    float acc[4][4][4];
#pragma unroll
    for (int mi = 0; mi < 4; mi++)
#pragma unroll
        for (int ni = 0; ni < 4; ni++)
#pragma unroll
            for (int r = 0; r < 4; r++) acc[mi][ni][r] = 0.f;

    float4 av0, av1, wv0, wv1;
    {   // prefetch first tile
        bool s1 = (0 + fq * 4) < K1;
        av0 = *(const float4*)((s1 ? a1p0 : a2p0));
        av1 = *(const float4*)((s1 ? a1p1 : a2p1));
        wv0 = *(const float4*)((s1 ? w1p0 : w2p0));
        wv1 = *(const float4*)((s1 ? w1p1 : w2p1));
    }

    for (int kt = 0; kt < KT; kt += 16) {
        __syncthreads();
        // commit prefetched data (convert fp32 -> tf32, scatter into chunks)
        sa0[((0 + fm0) & 3) * 4] = __uint_as_float(f2tf(av0.x));
        sa0[((1 + fm0) & 3) * 4] = __uint_as_float(f2tf(av0.y));
        sa0[((2 + fm0) & 3) * 4] = __uint_as_float(f2tf(av0.z));
        sa0[((3 + fm0) & 3) * 4] = __uint_as_float(f2tf(av0.w));
        sa1[((0 + fm1) & 3) * 4] = __uint_as_float(f2tf(av1.x));
        sa1[((1 + fm1) & 3) * 4] = __uint_as_float(f2tf(av1.y));
        sa1[((2 + fm1) & 3) * 4] = __uint_as_float(f2tf(av1.z));
        sa1[((3 + fm1) & 3) * 4] = __uint_as_float(f2tf(av1.w));
        sw0[((0 + fm0) & 3) * 4] = __uint_as_float(f2tf(wv0.x));
        sw0[((1 + fm0) & 3) * 4] = __uint_as_float(f2tf(wv0.y));
        sw0[((2 + fm0) & 3) * 4] = __uint_as_float(f2tf(wv0.z));
        sw0[((3 + fm0) & 3) * 4] = __uint_as_float(f2tf(wv0.w));
        sw1[((0 + fm1) & 3) * 4] = __uint_as_float(f2tf(wv1.x));
        sw1[((1 + fm1) & 3) * 4] = __uint_as_float(f2tf(wv1.y));
        sw1[((2 + fm1) & 3) * 4] = __uint_as_float(f2tf(wv1.z));
        sw1[((3 + fm1) & 3) * 4] = __uint_as_float(f2tf(wv1.w));
        __syncthreads();

        int kn = kt + 16;
        if (kn < KT) {     // prefetch next tile during compute
            bool s1 = (kn + fq * 4) < K1;
            av0 = *(const float4*)((s1 ? a1p0 : a2p0) + kn);
            av1 = *(const float4*)((s1 ? a1p1 : a2p1) + kn);
            wv0 = *(const float4*)((s1 ? w1p0 : w2p0) + kn);
            wv1 = *(const float4*)((s1 ? w1p1 : w2p1) + kn);
        }

        uint4 al[4], ah[4], bb[4];
#pragma unroll
        for (int mi = 0; mi < 4; mi++) {
            al[mi] = *(const uint4*)(As + aoff[mi]);
            ah[mi] = *(const uint4*)(As + aoff[mi] + 128);   // row +8
        }
#pragma unroll
        for (int ni = 0; ni < 4; ni++)
            bb[ni] = *(const uint4*)(Ws + boff[ni]);

#pragma unroll
        for (int mi = 0; mi < 4; mi++)
#pragma unroll
            for (int ni = 0; ni < 4; ni++) {
                mma8(acc[mi][ni], al[mi].x, ah[mi].x, al[mi].y, ah[mi].y,
                     bb[ni].x, bb[ni].y);                     // k-step 0
                mma8(acc[mi][ni], al[mi].z, ah[mi].z, al[mi].w, ah[mi].w,
                     bb[ni].z, bb[ni].w);                     // k-step 1
            }
    }

    // epilogue: + bias, write Z
#pragma unroll
    for (int mi = 0; mi < 4; mi++) {
        int gm = m0 + wm + mi * 16 + gid;
#pragma unroll
        for (int ni = 0; ni < 4; ni++) {
            int gn = n0 + wn + ni * 8 + t4 * 2;
            float b0 = bih[gn] + bhh[gn];
            float b1 = bih[gn + 1] + bhh[gn + 1];
            float2 lo = make_float2(acc[mi][ni][0] + b0, acc[mi][ni][1] + b1);
            float2 hi = make_float2(acc[mi][ni][2] + b0, acc[mi][ni][3] + b1);
            *(float2*)&g_z[(size_t)gm * G4 + gn]       = lo;
            *(float2*)&g_z[(size_t)(gm + 8) * G4 + gn] = hi;
        }
    }
}

// ---------------- gates phase ----------------------------------------------
__device__ void gates_phase(int layer)
{
    float* h = g_h01 + (layer ? 512 : 0);
    float* c = layer ? g_c1 : g_c0;
    const int g = blockIdx.x * NTHR + threadIdx.x;
#pragma unroll
    for (int it = 0; it < 4; it++) {
        int f4 = g + it * (NBLK * NTHR);
        int e  = f4 * 4;
        int b  = e >> 9;
        int j  = e & 511;
        const float* zr = g_z + (size_t)b * G4 + j;
        float4 zi = *(const float4*)(zr);
        float4 zf = *(const float4*)(zr + 512);
        float4 zg = *(const float4*)(zr + 1024);
        float4 zo = *(const float4*)(zr + 1536);
        float* cp = c + (size_t)b * HD + j;
        float4 cc = *(const float4*)cp;
        float4 nc, nh;
        nc.x = sigf(zf.x) * cc.x + sigf(zi.x) * tanhf(zg.x);
        nc.y = sigf(zf.y) * cc.y + sigf(zi.y) * tanhf(zg.y);
        nc.z = sigf(zf.z) * cc.z + sigf(zi.z) * tanhf(zg.z);
        nc.w = sigf(zf.w) * cc.w + sigf(zi.w) * tanhf(zg.w);
        nh.x = sigf(zo.x) * tanhf(nc.x);
        nh.y = sigf(zo.y) * tanhf(nc.y);
        nh.z = sigf(zo.z) * tanhf(nc.z);
        nh.w = sigf(zo.w) * tanhf(nc.w);
        *(float4*)cp = nc;
        float4 hh;   // pre-round h to tf32 so subsequent GEMM conversion is exact
        hh.x = __uint_as_float(f2tf(nh.x));
        hh.y = __uint_as_float(f2tf(nh.y));
        hh.z = __uint_as_float(f2tf(nh.z));
        hh.w = __uint_as_float(f2tf(nh.w));
        *(float4*)(h + (size_t)b * 1024 + j) = hh;
    }
}

// ---------------- fc phase (decoder projection) ----------------------------
__device__ void fc_phase(const float* __restrict__ fcw,
                         const float* __restrict__ fcb,
                         float* __restrict__ out, int t)
{
    const int r  = blockIdx.x * 8 + (threadIdx.x >> 5);
    const int c0 = (threadIdx.x & 31) * 4;
    const float* hrow = g_h01 + (size_t)r * 1024 + 512;
    const float* w0 = fcw + (size_t)(c0 + 0) * HD;
    const float* w1 = fcw + (size_t)(c0 + 1) * HD;
    const float* w2 = fcw + (size_t)(c0 + 2) * HD;
    const float* w3 = fcw + (size_t)(c0 + 3) * HD;
    float a0 = 0.f, a1 = 0.f, a2 = 0.f, a3 = 0.f;
#pragma unroll 4
    for (int k = 0; k < HD; k += 4) {
        float4 h4 = *(const float4*)(hrow + k);
        float4 v0 = *(const float4*)(w0 + k);
        float4 v1 = *(const float4*)(w1 + k);
        float4 v2 = *(const float4*)(w2 + k);
        float4 v3 = *(const float4*)(w3 + k);
        a0 += h4.x * v0.x + h4.y * v0.y + h4.z * v0.z + h4.w * v0.w;
        a1 += h4.x * v1.x + h4.y * v1.y + h4.z * v1.z + h4.w * v1.w;
        a2 += h4.x * v2.x + h4.y * v2.y + h4.z * v2.z + h4.w * v2.w;
        a3 += h4.x * v3.x + h4.y * v3.y + h4.z * v3.z + h4.w * v3.w;
    }
    float4 res;
    res.x = a0 + fcb[c0 + 0];
    res.y = a1 + fcb[c0 + 1];
    res.z = a2 + fcb[c0 + 2];
    res.w = a3 + fcb[c0 + 3];
    *(float4*)(out + (size_t)r * (TDEC * ID) + (size_t)t * ID + c0) = res;
    float4 dv;   // decoder feedback: tf32-rounded
    dv.x = __uint_as_float(f2tf(res.x));
    dv.y = __uint_as_float(f2tf(res.y));
    dv.z = __uint_as_float(f2tf(res.z));
    dv.w = __uint_as_float(f2tf(res.w));
    *(float4*)(g_din + (size_t)r * ID + c0) = dv;
}

// ---------------- persistent kernel ----------------------------------------
__global__ __launch_bounds__(NTHR, 1)
void lstm_persistent(const float* __restrict__ x,
                     const float* __restrict__ Wih0, const float* __restrict__ Whh0,
                     const float* __restrict__ bih0, const float* __restrict__ bhh0,
                     const float* __restrict__ Wih1, const float* __restrict__ Whh1,
                     const float* __restrict__ bih1, const float* __restrict__ bhh1,
                     const float* __restrict__ fcw,  const float* __restrict__ fcb,
                     float* __restrict__ out)
{
    __shared__ float sbuf[2 * 128 * 16];   // 16 KB: As | Ws

    init_phase(x);
    gridbar();

    for (int t = 0; t < TENC; t++) {
        gemm_phase<640, 128>(sbuf, x + (size_t)t * ID, TENC * ID,
                             g_h01, 1024, Wih0, Whh0, bih0, bhh0);
        gridbar();
        gates_phase(0);
        gridbar();
        gemm_phase<1024, 512>(sbuf, g_h01, 1024, g_h01 + 512, 1024,
                              Wih1, Whh1, bih1, bhh1);
        gridbar();
        gates_phase(1);
        gridbar();
    }

    for (int t = 0; t < TDEC; t++) {
        gemm_phase<640, 128>(sbuf, g_din, ID,
                             g_h01, 1024, Wih0, Whh0, bih0, bhh0);
        gridbar();
        gates_phase(0);
        gridbar();
        gemm_phase<1024, 512>(sbuf, g_h01, 1024, g_h01 + 512, 1024,
                              Wih1, Whh1, bih1, bhh1);
        gridbar();
        gates_phase(1);
        gridbar();
        fc_phase(fcw, fcb, out, t);
        gridbar();
    }
}

// ---------------- entry -----------------------------------------------------
extern "C" void kernel_launch(void* const* d_in, const int* in_sizes, int n_in,
                              void* d_out, int out_size)
{
    lstm_persistent<<<NBLK, NTHR>>>(
        (const float*)d_in[0],
        (const float*)d_in[1], (const float*)d_in[2],
        (const float*)d_in[3], (const float*)d_in[4],
        (const float*)d_in[5], (const float*)d_in[6],
        (const float*)d_in[7], (const float*)d_in[8],
        (const float*)d_in[9], (const float*)d_in[10],
        (float*)d_out);
}